// round 1
// baseline (speedup 1.0000x reference)
#include <cuda_runtime.h>
#include <cstdint>

// Problem constants
#define B_ 512
#define T_ 64
#define D_ 512
#define H_ 256
#define A_ 256
#define C_ 96
#define STEPS_ 26
#define G_ 768     // A_ + D_
#define H3_ 768    // 3*H_
#define NB 4       // batch rows per attention block

// ---------------- device scratch (no allocations allowed) ----------------
__device__ float g_xProj[(size_t)B_ * T_ * A_];   // [B,T,A]  33.5 MB
__device__ float g_h [B_ * H_];                   // hidden state
__device__ float g_g [B_ * G_];                   // [emb(y) | ctx]
__device__ float g_gi[B_ * H3_];
__device__ float g_gh[B_ * H3_];

// ---------------- helpers ----------------
__device__ __forceinline__ float tanh_fast(float x) {
    float y; asm("tanh.approx.f32 %0, %1;" : "=f"(y) : "f"(x)); return y;
}
__device__ __forceinline__ float sigmoid_f(float x) {
    return 1.0f / (1.0f + __expf(-x));
}
__device__ __forceinline__ float warp_sum(float v) {
    #pragma unroll
    for (int o = 16; o; o >>= 1) v += __shfl_xor_sync(0xffffffffu, v, o);
    return v;
}
__device__ __forceinline__ float warp_max(float v) {
    #pragma unroll
    for (int o = 16; o; o >>= 1) v = fmaxf(v, __shfl_xor_sync(0xffffffffu, v, o));
    return v;
}

// ---------------- generic fp32 tiled GEMM:  C[m,n] = sum_k A[m,k]*W[n,k] + bias[n] ----------------
// 64x64 tile, BK=16, 256 threads, 4x4 microtile, float4 smem loads.
// All of M, N must be multiples of 64 and K a multiple of 16 (true for every call here).
__device__ __forceinline__ void sgemm_core(
    const float* __restrict__ A, const float* __restrict__ W,
    const float* __restrict__ bias, float* __restrict__ C,
    int K, int N, int mtile, int ntile)
{
    __shared__ float As[16][68];
    __shared__ float Bs[16][68];

    const int tid = threadIdx.x;
    const int tx = tid & 15;        // 0..15 -> n micro
    const int ty = tid >> 4;        // 0..15 -> m micro
    const int lrow = tid >> 2;      // 0..63 load row
    const int lc   = tid & 3;       // 0..3  float4 chunk of k

    const int m0 = mtile * 64;
    const int n0 = ntile * 64;

    float acc[4][4] = {};

    const float* Arow = A + (size_t)(m0 + lrow) * K;
    const float* Wrow = W + (size_t)(n0 + lrow) * K;

    for (int k0 = 0; k0 < K; k0 += 16) {
        float4 av = *(const float4*)(Arow + k0 + lc * 4);
        float4 bv = *(const float4*)(Wrow + k0 + lc * 4);
        __syncthreads();
        As[lc * 4 + 0][lrow] = av.x;  As[lc * 4 + 1][lrow] = av.y;
        As[lc * 4 + 2][lrow] = av.z;  As[lc * 4 + 3][lrow] = av.w;
        Bs[lc * 4 + 0][lrow] = bv.x;  Bs[lc * 4 + 1][lrow] = bv.y;
        Bs[lc * 4 + 2][lrow] = bv.z;  Bs[lc * 4 + 3][lrow] = bv.w;
        __syncthreads();

        #pragma unroll
        for (int kk = 0; kk < 16; kk++) {
            float4 a4 = *(const float4*)&As[kk][ty * 4];
            float4 b4 = *(const float4*)&Bs[kk][tx * 4];
            float ar[4] = {a4.x, a4.y, a4.z, a4.w};
            float br[4] = {b4.x, b4.y, b4.z, b4.w};
            #pragma unroll
            for (int i = 0; i < 4; i++)
                #pragma unroll
                for (int j = 0; j < 4; j++)
                    acc[i][j] += ar[i] * br[j];
        }
    }

    float4 bias4 = *(const float4*)(bias + n0 + tx * 4);
    float bb[4] = {bias4.x, bias4.y, bias4.z, bias4.w};
    #pragma unroll
    for (int i = 0; i < 4; i++) {
        float4 o4;
        o4.x = acc[i][0] + bb[0];
        o4.y = acc[i][1] + bb[1];
        o4.z = acc[i][2] + bb[2];
        o4.w = acc[i][3] + bb[3];
        *(float4*)(C + (size_t)(m0 + ty * 4 + i) * N + n0 + tx * 4) = o4;
    }
}

// ---------------- kernels ----------------
__global__ void init_kernel() {
    int i = blockIdx.x * 256 + threadIdx.x;
    if (i < B_ * H_) g_h[i] = 0.0f;
}

// xProj[B*T, A] = img[B*T, D] @ Wx[A, D]^T + bx
__global__ void xproj_kernel(const float* __restrict__ img,
                             const float* __restrict__ Wx,
                             const float* __restrict__ bx) {
    sgemm_core(img, Wx, bx, g_xProj, D_, A_, blockIdx.y, blockIdx.x);
}

// z==0: gi[512,768] = g[512,768] @ Wih[768,768]^T + bih
// z==1: gh[512,768] = h[512,256] @ Whh[768,256]^T + bhh
__global__ void gru_gemm_kernel(const float* __restrict__ Wih,
                                const float* __restrict__ bih,
                                const float* __restrict__ Whh,
                                const float* __restrict__ bhh) {
    if (blockIdx.z == 0)
        sgemm_core(g_g, Wih, bih, g_gi, G_, H3_, blockIdx.y, blockIdx.x);
    else
        sgemm_core(g_h, Whh, bhh, g_gh, H_, H3_, blockIdx.y, blockIdx.x);
}

// Fused: (GRU gates from previous step's gi/gh -> h_new, FC output), then
// attention for the current step (sProj, scores, softmax, ctx, build g row).
// step == 0     : h = 0, no gates/out, attention only.
// step == STEPS : gates + out only (final output row), no attention.
__global__ void att_kernel(int step,
                           const float* __restrict__ img,
                           const int*   __restrict__ label,
                           const float* __restrict__ Ws,
                           const float* __restrict__ bs,
                           const float* __restrict__ Ww,
                           const float* __restrict__ bw,
                           const float* __restrict__ emb,
                           const float* __restrict__ Wfc,
                           const float* __restrict__ bfc,
                           float* __restrict__ out) {
    __shared__ float hs[NB][H_];
    __shared__ float sp[NB][A_];
    __shared__ float ww_s[A_];
    __shared__ float vb[NB][T_];
    __shared__ float al[NB][T_];

    const int tid  = threadIdx.x;
    const int lane = tid & 31;
    const int w    = tid >> 5;           // warp id 0..7
    const int b0   = blockIdx.x * NB;

    if (tid < A_) ww_s[tid] = Ww[tid];

    // ---- Phase A: hidden update (gates) ----
    if (step == 0) {
        for (int i = tid; i < NB * H_; i += 256) hs[i / H_][i % H_] = 0.0f;
    } else {
        for (int i = tid; i < NB * H_; i += 256) {
            int b = i / H_, j = i % H_;
            int row = b0 + b;
            const float* gi = g_gi + (size_t)row * H3_;
            const float* gh = g_gh + (size_t)row * H3_;
            float r  = sigmoid_f(gi[j]            + gh[j]);
            float z  = sigmoid_f(gi[H_ + j]       + gh[H_ + j]);
            float nn = tanhf(gi[2 * H_ + j] + r * gh[2 * H_ + j]);
            float hp = g_h[(size_t)row * H_ + j];
            float hn = (1.0f - z) * nn + z * hp;
            hs[b][j] = hn;
            g_h[(size_t)row * H_ + j] = hn;
        }
    }
    __syncthreads();

    // ---- Phase B: FC output for step-1 (needs h_new) ----
    if (step > 0) {
        for (int o = w; o < NB * C_; o += 8) {
            int b = o / C_, c = o % C_;
            const float* wr = Wfc + (size_t)c * H_;
            float acc = 0.0f;
            #pragma unroll
            for (int i = 0; i < H_; i += 32) acc += wr[i + lane] * hs[b][i + lane];
            acc = warp_sum(acc);
            if (lane == 0)
                out[((size_t)(b0 + b) * STEPS_ + (step - 1)) * C_ + c] = acc + bfc[c];
        }
    }
    if (step >= STEPS_) return;    // final pass: output only
    __syncthreads();

    // ---- Phase C: sProj = h @ Ws^T + bs  (4 batch rows at once) ----
    for (int ii = 0; ii < 32; ii++) {
        int a = w * 32 + ii;
        const float* wr = Ws + (size_t)a * H_;
        float a0 = 0.f, a1 = 0.f, a2 = 0.f, a3 = 0.f;
        #pragma unroll
        for (int k = lane; k < H_; k += 32) {
            float wv = wr[k];
            a0 += wv * hs[0][k];
            a1 += wv * hs[1][k];
            a2 += wv * hs[2][k];
            a3 += wv * hs[3][k];
        }
        a0 = warp_sum(a0); a1 = warp_sum(a1); a2 = warp_sum(a2); a3 = warp_sum(a3);
        if (lane == 0) {
            float bb = bs[a];
            sp[0][a] = a0 + bb; sp[1][a] = a1 + bb;
            sp[2][a] = a2 + bb; sp[3][a] = a3 + bb;
        }
    }
    __syncthreads();

    // ---- Phase D: attention scores v[b,t] ----
    {
        const int b = w >> 1;
        const int tbase = (w & 1) * 32;
        const float bw0 = bw[0];
        for (int tt = 0; tt < 32; tt++) {
            int t = tbase + tt;
            const float* xp = g_xProj + ((size_t)(b0 + b) * T_ + t) * A_;
            float acc = 0.0f;
            #pragma unroll
            for (int i = lane; i < A_; i += 32)
                acc += tanh_fast(sp[b][i] + xp[i]) * ww_s[i];
            acc = warp_sum(acc);
            if (lane == 0) vb[b][t] = acc + bw0;
        }
    }
    __syncthreads();

    // ---- Phase E: softmax over T (one warp per batch row) ----
    if (w < NB) {
        float v0 = vb[w][lane], v1 = vb[w][lane + 32];
        float m = warp_max(fmaxf(v0, v1));
        float e0 = __expf(v0 - m), e1 = __expf(v1 - m);
        float s = warp_sum(e0 + e1);
        float inv = 1.0f / s;
        al[w][lane]      = e0 * inv;
        al[w][lane + 32] = e1 * inv;
    }
    __syncthreads();

    // ---- Phase F: ctx = alpha @ img, write g = [emb(y) | ctx] ----
    for (int i = tid; i < NB * D_; i += 256) {
        int b = i / D_, d = i % D_;
        const float* ib = img + ((size_t)(b0 + b) * T_) * D_ + d;
        float acc = 0.0f;
        #pragma unroll 8
        for (int t = 0; t < T_; t++) acc += al[b][t] * ib[(size_t)t * D_];
        g_g[(size_t)(b0 + b) * G_ + A_ + d] = acc;
    }
    for (int i = tid; i < NB * A_; i += 256) {
        int b = i / A_, j = i % A_;
        int y = (step == 0) ? 0 : label[(b0 + b) * STEPS_ + step];
        g_g[(size_t)(b0 + b) * G_ + j] = emb[(size_t)y * A_ + j];
    }
}

// ---------------- host launch ----------------
extern "C" void kernel_launch(void* const* d_in, const int* in_sizes, int n_in,
                              void* d_out, int out_size) {
    const float* img   = (const float*)d_in[0];
    const int*   label = (const int*)  d_in[1];
    const float* Wx    = (const float*)d_in[2];
    const float* bx    = (const float*)d_in[3];
    const float* Ws    = (const float*)d_in[4];
    const float* bs    = (const float*)d_in[5];
    const float* Ww    = (const float*)d_in[6];
    const float* bw    = (const float*)d_in[7];
    const float* emb   = (const float*)d_in[8];
    const float* Wih   = (const float*)d_in[9];
    const float* bih   = (const float*)d_in[10];
    const float* Whh   = (const float*)d_in[11];
    const float* bhh   = (const float*)d_in[12];
    const float* Wfc   = (const float*)d_in[13];
    const float* bfc   = (const float*)d_in[14];
    float* out = (float*)d_out;

    init_kernel<<<(B_ * H_ + 255) / 256, 256>>>();

    // xProj: M = B*T = 32768, N = A = 256, K = D = 512
    dim3 gx(A_ / 64, (B_ * T_) / 64);
    xproj_kernel<<<gx, 256>>>(img, Wx, bx);

    dim3 gg(H3_ / 64, B_ / 64, 2);   // 12 x 8 x 2 = 192 blocks
    for (int s = 0; s < STEPS_; s++) {
        att_kernel<<<B_ / NB, 256>>>(s, img, label, Ws, bs, Ww, bw, emb, Wfc, bfc, out);
        gru_gemm_kernel<<<gg, 256>>>(Wih, bih, Whh, bhh);
    }
    // final hidden update + last output row
    att_kernel<<<B_ / NB, 256>>>(STEPS_, img, label, Ws, bs, Ww, bw, emb, Wfc, bfc, out);
}

// round 2
// speedup vs baseline: 1.0143x; 1.0143x over previous
#include <cuda_runtime.h>
#include <cstdint>

#define B_ 512
#define T_ 64
#define D_ 512
#define H_ 256
#define A_ 256
#define C_ 96
#define STEPS_ 26
#define H3_ 768

// ---------------- device scratch ----------------
__device__ float g_xProjT[(size_t)B_ * A_ * T_];   // [B, A, T] transposed! 33.5MB
__device__ float g_h[B_ * H_];
__device__ float g_ctx[B_ * D_];
__device__ float g_gi0[B_ * H3_];
__device__ float g_gi1[B_ * H3_];
__device__ float g_gh0[B_ * H3_];
__device__ float g_gh1[B_ * H3_];
__device__ float g_WihCtx[H3_ * D_];               // Wih[:, 256:768] packed
__device__ float g_WihEmbT[A_ * H3_];              // transpose of Wih[:, :256]
__device__ float g_WsT[H_ * A_];                   // [k][a]
__device__ float g_WfcT[H_ * C_];                  // [k][c]
__device__ float g_embProj[(C_ + 1) * H3_];        // emb @ Wih[:, :256]^T + bih

// ---------------- helpers ----------------
__device__ __forceinline__ float tanh_fast(float x) {
    float y; asm("tanh.approx.f32 %0, %1;" : "=f"(y) : "f"(x)); return y;
}
__device__ __forceinline__ float sigmoid_f(float x) {
    return 1.0f / (1.0f + __expf(-x));
}
__device__ __forceinline__ float warp_sum(float v) {
    #pragma unroll
    for (int o = 16; o; o >>= 1) v += __shfl_xor_sync(0xffffffffu, v, o);
    return v;
}
__device__ __forceinline__ float warp_max(float v) {
    #pragma unroll
    for (int o = 16; o; o >>= 1) v = fmaxf(v, __shfl_xor_sync(0xffffffffu, v, o));
    return v;
}

// ---------------- setup: zero h + weight transposes/packs ----------------
__global__ void setup_kernel(const float* __restrict__ Ws,
                             const float* __restrict__ Wfc,
                             const float* __restrict__ Wih) {
    int idx = blockIdx.x * 256 + threadIdx.x;
    int stride = gridDim.x * 256;
    for (int i = idx; i < B_ * H_; i += stride) g_h[i] = 0.0f;
    for (int i = idx; i < H_ * A_; i += stride) {
        int k = i >> 8, a = i & 255;
        g_WsT[i] = Ws[a * H_ + k];
    }
    for (int i = idx; i < H_ * C_; i += stride) {
        int k = i / C_, c = i - k * C_;
        g_WfcT[i] = Wfc[c * H_ + k];
    }
    for (int i = idx; i < H3_ * D_; i += stride) {
        int n = i >> 9, k = i & 511;
        g_WihCtx[i] = Wih[n * (D_ + A_) + A_ + k];
    }
    for (int i = idx; i < A_ * H3_; i += stride) {
        int k = i / H3_, n = i - k * H3_;
        g_WihEmbT[i] = Wih[n * (D_ + A_) + k];
    }
}

// embProj[y][n] = sum_k emb[y][k] * Wih[n][k] + bih[n]
__global__ __launch_bounds__(256) void embproj_kernel(const float* __restrict__ emb,
                                                      const float* __restrict__ bih) {
    __shared__ float es[A_];
    int y = blockIdx.x, tid = threadIdx.x;
    es[tid] = emb[y * A_ + tid];
    __syncthreads();
    for (int nn = tid; nn < H3_; nn += 256) {
        float acc = bih[nn];
        #pragma unroll 8
        for (int k = 0; k < A_; k++) acc += g_WihEmbT[k * H3_ + nn] * es[k];
        g_embProj[y * H3_ + nn] = acc;
    }
}

// ---------------- xproj: 128x128x16 double-buffered GEMM, transposed store ----------------
// xProjT[b][a][t] = sum_d img[b][t][d]*Wx[a][d] + bx[a]
__global__ __launch_bounds__(256) void xproj_kernel(const float* __restrict__ img,
                                                    const float* __restrict__ Wx,
                                                    const float* __restrict__ bx) {
    __shared__ float As[2][16][132];
    __shared__ float Bs[2][16][132];
    const int tid = threadIdx.x;
    const int tx = tid & 15, ty = tid >> 4;
    const int lrow = tid >> 2, lc = tid & 3;
    const int n0 = blockIdx.x * 128;   // A dim
    const int m0 = blockIdx.y * 128;   // (b,t) dim

    const float* Ap  = img + (size_t)(m0 + lrow) * D_ + lc * 4;
    const float* Ap2 = Ap + (size_t)64 * D_;
    const float* Wp  = Wx + (size_t)(n0 + lrow) * D_ + lc * 4;
    const float* Wp2 = Wp + (size_t)64 * D_;

    float acc[8][8] = {};
    float4 a0 = *(const float4*)Ap;
    float4 a1 = *(const float4*)Ap2;
    float4 w0 = *(const float4*)Wp;
    float4 w1 = *(const float4*)Wp2;

    int buf = 0;
    #define XST(BUF) do { \
        As[BUF][lc*4+0][lrow]=a0.x; As[BUF][lc*4+1][lrow]=a0.y; As[BUF][lc*4+2][lrow]=a0.z; As[BUF][lc*4+3][lrow]=a0.w; \
        As[BUF][lc*4+0][lrow+64]=a1.x; As[BUF][lc*4+1][lrow+64]=a1.y; As[BUF][lc*4+2][lrow+64]=a1.z; As[BUF][lc*4+3][lrow+64]=a1.w; \
        Bs[BUF][lc*4+0][lrow]=w0.x; Bs[BUF][lc*4+1][lrow]=w0.y; Bs[BUF][lc*4+2][lrow]=w0.z; Bs[BUF][lc*4+3][lrow]=w0.w; \
        Bs[BUF][lc*4+0][lrow+64]=w1.x; Bs[BUF][lc*4+1][lrow+64]=w1.y; Bs[BUF][lc*4+2][lrow+64]=w1.z; Bs[BUF][lc*4+3][lrow+64]=w1.w; \
    } while(0)
    #define XCOMP(BUF) do { \
        _Pragma("unroll") \
        for (int kk = 0; kk < 16; kk++) { \
            float4 av0 = *(const float4*)&As[BUF][kk][ty*8]; \
            float4 av1 = *(const float4*)&As[BUF][kk][ty*8+4]; \
            float4 bv0 = *(const float4*)&Bs[BUF][kk][tx*8]; \
            float4 bv1 = *(const float4*)&Bs[BUF][kk][tx*8+4]; \
            float ar[8] = {av0.x,av0.y,av0.z,av0.w,av1.x,av1.y,av1.z,av1.w}; \
            float br[8] = {bv0.x,bv0.y,bv0.z,bv0.w,bv1.x,bv1.y,bv1.z,bv1.w}; \
            _Pragma("unroll") \
            for (int i = 0; i < 8; i++) \
                _Pragma("unroll") \
                for (int j = 0; j < 8; j++) acc[i][j] += ar[i]*br[j]; \
        } \
    } while(0)

    XST(0);
    __syncthreads();
    for (int k0 = 16; k0 < D_; k0 += 16) {
        a0 = *(const float4*)(Ap + k0);
        a1 = *(const float4*)(Ap2 + k0);
        w0 = *(const float4*)(Wp + k0);
        w1 = *(const float4*)(Wp2 + k0);
        if (buf == 0) { XCOMP(0); XST(1); } else { XCOMP(1); XST(0); }
        __syncthreads();
        buf ^= 1;
    }
    if (buf == 0) XCOMP(0); else XCOMP(1);

    float bxr[8];
    #pragma unroll
    for (int j = 0; j < 8; j++) bxr[j] = bx[n0 + tx * 8 + j];
    #pragma unroll
    for (int i = 0; i < 8; i++) {
        int m = m0 + ty * 8 + i;
        int b = m >> 6, t = m & 63;
        #pragma unroll
        for (int j = 0; j < 8; j++) {
            int a = n0 + tx * 8 + j;
            g_xProjT[(size_t)b * (A_ * T_) + a * T_ + t] = acc[i][j] + bxr[j];
        }
    }
    #undef XST
    #undef XCOMP
}

// ---------------- per-step GEMM: 64x64x16 double-buffered, split-K, no bias ----------------
// z=0/1: gi split halves (ctx @ WihCtx^T, K=512); z=2/3: gh halves (h @ Whh^T, K=256)
__global__ __launch_bounds__(256) void step_gemm(const float* __restrict__ Whh) {
    __shared__ float As[2][16][68];
    __shared__ float Bs[2][16][68];
    const int z = blockIdx.z;
    const float* A; int as_; const float* W; int ws_; float* C; int koff, klen;
    if (z < 2) { A = g_ctx; as_ = D_; W = g_WihCtx; ws_ = D_;
                 C = z ? g_gi1 : g_gi0; koff = z * 256; klen = 256; }
    else       { A = g_h;   as_ = H_; W = Whh;      ws_ = H_;
                 C = (z == 3) ? g_gh1 : g_gh0; koff = (z - 2) * 128; klen = 128; }

    const int tid = threadIdx.x;
    const int tx = tid & 15, ty = tid >> 4;
    const int lrow = tid >> 2, lc = tid & 3;
    const int n0 = blockIdx.x * 64;
    const int m0 = blockIdx.y * 64;

    float acc[4][4] = {};
    const float* Ap = A + (size_t)(m0 + lrow) * as_ + koff + lc * 4;
    const float* Wp = W + (size_t)(n0 + lrow) * ws_ + koff + lc * 4;
    float4 av = *(const float4*)Ap;
    float4 bv = *(const float4*)Wp;

    #define GST(BUF) do { \
        As[BUF][lc*4+0][lrow]=av.x; As[BUF][lc*4+1][lrow]=av.y; As[BUF][lc*4+2][lrow]=av.z; As[BUF][lc*4+3][lrow]=av.w; \
        Bs[BUF][lc*4+0][lrow]=bv.x; Bs[BUF][lc*4+1][lrow]=bv.y; Bs[BUF][lc*4+2][lrow]=bv.z; Bs[BUF][lc*4+3][lrow]=bv.w; \
    } while(0)
    #define GCOMP(BUF) do { \
        _Pragma("unroll") \
        for (int kk = 0; kk < 16; kk++) { \
            float4 a4 = *(const float4*)&As[BUF][kk][ty*4]; \
            float4 b4 = *(const float4*)&Bs[BUF][kk][tx*4]; \
            float ar[4] = {a4.x,a4.y,a4.z,a4.w}; \
            float br[4] = {b4.x,b4.y,b4.z,b4.w}; \
            _Pragma("unroll") \
            for (int i = 0; i < 4; i++) \
                _Pragma("unroll") \
                for (int j = 0; j < 4; j++) acc[i][j] += ar[i]*br[j]; \
        } \
    } while(0)

    GST(0);
    __syncthreads();
    int buf = 0;
    for (int k0 = 16; k0 < klen; k0 += 16) {
        av = *(const float4*)(Ap + k0);
        bv = *(const float4*)(Wp + k0);
        if (buf == 0) { GCOMP(0); GST(1); } else { GCOMP(1); GST(0); }
        __syncthreads();
        buf ^= 1;
    }
    if (buf == 0) GCOMP(0); else GCOMP(1);

    #pragma unroll
    for (int i = 0; i < 4; i++) {
        float4 o4 = {acc[i][0], acc[i][1], acc[i][2], acc[i][3]};
        *(float4*)(C + (size_t)(m0 + ty * 4 + i) * H3_ + n0 + tx * 4) = o4;
    }
    #undef GST
    #undef GCOMP
}

// ---------------- fused gates + FC + attention ----------------
__global__ __launch_bounds__(256) void att_kernel(int step,
                           const float* __restrict__ img,
                           const int*   __restrict__ label,
                           const float* __restrict__ bs,
                           const float* __restrict__ Ww,
                           const float* __restrict__ bw,
                           const float* __restrict__ bhh,
                           const float* __restrict__ bfc,
                           float* __restrict__ out) {
    __shared__ float hs[4][H_];
    __shared__ float sp[4][A_];
    __shared__ float ww_s[A_];
    __shared__ float vb[4][T_];
    __shared__ float al[4][T_];

    const int tid  = threadIdx.x;
    const int lane = tid & 31;
    const int w    = tid >> 5;
    const int b0   = blockIdx.x * 4;

    if (tid < A_) ww_s[tid] = Ww[tid];

    // ---- Phase A: GRU gates (h update for step-1) ----
    if (step == 0) {
        for (int i = tid; i < 4 * H_; i += 256) hs[i >> 8][i & 255] = 0.0f;
    } else {
        for (int i = tid; i < 4 * H_; i += 256) {
            int b = i >> 8, j = i & 255, row = b0 + b;
            int yp = (step == 1) ? 0 : label[row * STEPS_ + step - 1];
            const float* ep = g_embProj + (size_t)yp * H3_;
            size_t o = (size_t)row * H3_ + j;
            float gir = ep[j]          + g_gi0[o]          + g_gi1[o];
            float giz = ep[H_ + j]     + g_gi0[o + H_]     + g_gi1[o + H_];
            float gin = ep[2 * H_ + j] + g_gi0[o + 2 * H_] + g_gi1[o + 2 * H_];
            float ghr = g_gh0[o]          + g_gh1[o]          + bhh[j];
            float ghz = g_gh0[o + H_]     + g_gh1[o + H_]     + bhh[H_ + j];
            float ghn = g_gh0[o + 2 * H_] + g_gh1[o + 2 * H_] + bhh[2 * H_ + j];
            float r  = sigmoid_f(gir + ghr);
            float zz = sigmoid_f(giz + ghz);
            float nn = tanhf(gin + r * ghn);
            float hp = g_h[(size_t)row * H_ + j];
            float hn = (1.0f - zz) * nn + zz * hp;
            hs[b][j] = hn;
            g_h[(size_t)row * H_ + j] = hn;
        }
    }
    __syncthreads();

    // ---- Phase B: FC out for step-1 ----
    if (step > 0) {
        for (int idx = tid; idx < 4 * C_; idx += 256) {
            int b = idx / C_, c = idx - b * C_;
            float acc = bfc[c];
            #pragma unroll 8
            for (int k = 0; k < H_; k++) acc += g_WfcT[k * C_ + c] * hs[b][k];
            out[((size_t)(b0 + b) * STEPS_ + step - 1) * C_ + c] = acc;
        }
    }
    if (step >= STEPS_) return;
    __syncthreads();

    // ---- Phase C: sProj = h @ Ws^T + bs (thread owns one a) ----
    {
        int a = tid;
        float a0 = 0.f, a1 = 0.f, a2 = 0.f, a3 = 0.f;
        #pragma unroll 4
        for (int k = 0; k < H_; k++) {
            float wv = g_WsT[k * A_ + a];
            a0 += wv * hs[0][k]; a1 += wv * hs[1][k];
            a2 += wv * hs[2][k]; a3 += wv * hs[3][k];
        }
        float bb = bs[a];
        sp[0][a] = a0 + bb; sp[1][a] = a1 + bb;
        sp[2][a] = a2 + bb; sp[3][a] = a3 + bb;
    }
    __syncthreads();

    // ---- Phase D: scores (thread owns one (b,t), coalesced xProjT) ----
    {
        int b = tid >> 6, t = tid & 63;
        const float* xp = g_xProjT + (size_t)(b0 + b) * (A_ * T_) + t;
        float acc = 0.0f;
        #pragma unroll 8
        for (int a = 0; a < A_; a++)
            acc += tanh_fast(sp[b][a] + xp[(size_t)a * T_]) * ww_s[a];
        vb[b][t] = acc + bw[0];
    }
    __syncthreads();

    // ---- Phase E: softmax over T ----
    if (w < 4) {
        float v0 = vb[w][lane], v1 = vb[w][lane + 32];
        float m = warp_max(fmaxf(v0, v1));
        float e0 = __expf(v0 - m), e1 = __expf(v1 - m);
        float s = warp_sum(e0 + e1);
        float inv = 1.0f / s;
        al[w][lane]      = e0 * inv;
        al[w][lane + 32] = e1 * inv;
    }
    __syncthreads();

    // ---- Phase F: ctx = alpha @ img (float4) ----
    const float4* img4 = (const float4*)img;
    for (int i = tid; i < 4 * (D_ / 4); i += 256) {
        int b = i >> 7, d4 = i & 127;
        const float4* ib = img4 + (size_t)(b0 + b) * T_ * (D_ / 4) + d4;
        float4 acc = {0.f, 0.f, 0.f, 0.f};
        #pragma unroll 8
        for (int t = 0; t < T_; t++) {
            float a = al[b][t];
            float4 iv = ib[(size_t)t * (D_ / 4)];
            acc.x += a * iv.x; acc.y += a * iv.y;
            acc.z += a * iv.z; acc.w += a * iv.w;
        }
        *(float4*)(g_ctx + (size_t)(b0 + b) * D_ + d4 * 4) = acc;
    }
}

// ---------------- host launch ----------------
extern "C" void kernel_launch(void* const* d_in, const int* in_sizes, int n_in,
                              void* d_out, int out_size) {
    const float* img   = (const float*)d_in[0];
    const int*   label = (const int*)  d_in[1];
    const float* Wx    = (const float*)d_in[2];
    const float* bx    = (const float*)d_in[3];
    const float* Ws    = (const float*)d_in[4];
    const float* bs    = (const float*)d_in[5];
    const float* Ww    = (const float*)d_in[6];
    const float* bw    = (const float*)d_in[7];
    const float* emb   = (const float*)d_in[8];
    const float* Wih   = (const float*)d_in[9];
    const float* bih   = (const float*)d_in[10];
    const float* Whh   = (const float*)d_in[11];
    const float* bhh   = (const float*)d_in[12];
    const float* Wfc   = (const float*)d_in[13];
    const float* bfc   = (const float*)d_in[14];
    float* out = (float*)d_out;

    setup_kernel<<<512, 256>>>(Ws, Wfc, Wih);
    embproj_kernel<<<C_ + 1, 256>>>(emb, bih);

    dim3 gx(A_ / 128, (B_ * T_) / 128);            // (2, 256)
    xproj_kernel<<<gx, 256>>>(img, Wx, bx);

    dim3 gg(H3_ / 64, B_ / 64, 4);                 // (12, 8, 4) = 384 blocks
    for (int s = 0; s < STEPS_; s++) {
        att_kernel<<<B_ / 4, 256>>>(s, img, label, bs, Ww, bw, bhh, bfc, out);
        step_gemm<<<gg, 256>>>(Whh);
    }
    att_kernel<<<B_ / 4, 256>>>(STEPS_, img, label, bs, Ww, bw, bhh, bfc, out);
}

// round 3
// speedup vs baseline: 1.8400x; 1.8140x over previous
#include <cuda_runtime.h>
#include <cstdint>

#define B_ 512
#define T_ 64
#define D_ 512
#define H_ 256
#define A_ 256
#define C_ 96
#define STEPS_ 26
#define H3_ 768

// ---------------- device scratch ----------------
__device__ float g_xProjT[(size_t)B_ * A_ * T_];   // [B, A, T]
__device__ float g_h[B_ * H_];
__device__ float g_ctx[B_ * D_];
__device__ float g_sp[B_ * A_];
__device__ float g_gi0[B_ * H3_];
__device__ float g_gi1[B_ * H3_];
__device__ float g_gh0[B_ * H3_];
__device__ float g_gh1[B_ * H3_];
__device__ float g_WihCtx[H3_ * D_];               // Wih[:, 256:768]
__device__ float g_WihEmbT[A_ * H3_];              // Wih[:, :256]^T
__device__ float g_WsT[H_ * A_];
__device__ float g_WfcT[H_ * C_];
__device__ float g_embProj[(C_ + 1) * H3_];

// ---------------- FMA-only tanh (no MUFU): Pade(5,4) + Newton reciprocal ----
__device__ __forceinline__ float fma_tanh(float x) {
    x = fminf(3.2f, fmaxf(-3.2f, x));
    float u = x * x;
    float num = x * (945.0f + u * (105.0f + u));
    float den = 945.0f + u * (420.0f + u * 15.0f);
    float y = 1.0582e-3f + u * (-2.1408e-4f + u * 1.2184e-5f);   // seed ~1/den
    y = y * (2.0f - den * y);
    y = y * (2.0f - den * y);
    y = y * (2.0f - den * y);
    return num * y;
}
__device__ __forceinline__ float fma_sigmoid(float x) {
    return 0.5f + 0.5f * fma_tanh(0.5f * x);
}
__device__ __forceinline__ float warp_sum(float v) {
    #pragma unroll
    for (int o = 16; o; o >>= 1) v += __shfl_xor_sync(0xffffffffu, v, o);
    return v;
}
__device__ __forceinline__ float warp_max(float v) {
    #pragma unroll
    for (int o = 16; o; o >>= 1) v = fmaxf(v, __shfl_xor_sync(0xffffffffu, v, o));
    return v;
}

// ---------------- setup ----------------
__global__ void setup_kernel(const float* __restrict__ Ws,
                             const float* __restrict__ Wfc,
                             const float* __restrict__ Wih) {
    int idx = blockIdx.x * 256 + threadIdx.x;
    int stride = gridDim.x * 256;
    for (int i = idx; i < B_ * H_; i += stride) g_h[i] = 0.0f;
    for (int i = idx; i < H_ * A_; i += stride) {
        int k = i >> 8, a = i & 255;
        g_WsT[i] = Ws[a * H_ + k];
    }
    for (int i = idx; i < H_ * C_; i += stride) {
        int k = i / C_, c = i - k * C_;
        g_WfcT[i] = Wfc[c * H_ + k];
    }
    for (int i = idx; i < H3_ * D_; i += stride) {
        int n = i >> 9, k = i & 511;
        g_WihCtx[i] = Wih[n * (D_ + A_) + A_ + k];
    }
    for (int i = idx; i < A_ * H3_; i += stride) {
        int k = i / H3_, n = i - k * H3_;
        g_WihEmbT[i] = Wih[n * (D_ + A_) + k];
    }
}

__global__ __launch_bounds__(256) void embproj_kernel(const float* __restrict__ emb,
                                                      const float* __restrict__ bih) {
    __shared__ float es[A_];
    int y = blockIdx.x, tid = threadIdx.x;
    es[tid] = emb[y * A_ + tid];
    __syncthreads();
    for (int nn = tid; nn < H3_; nn += 256) {
        float acc = bih[nn];
        #pragma unroll 8
        for (int k = 0; k < A_; k++) acc += g_WihEmbT[k * H3_ + nn] * es[k];
        g_embProj[y * H3_ + nn] = acc;
    }
}

// ---------------- xproj: 128x128x16 double-buffered GEMM, transposed store ----
__global__ __launch_bounds__(256) void xproj_kernel(const float* __restrict__ img,
                                                    const float* __restrict__ Wx,
                                                    const float* __restrict__ bx) {
    __shared__ float As[2][16][132];
    __shared__ float Bs[2][16][132];
    const int tid = threadIdx.x;
    const int tx = tid & 15, ty = tid >> 4;
    const int lrow = tid >> 2, lc = tid & 3;
    const int n0 = blockIdx.x * 128;
    const int m0 = blockIdx.y * 128;

    const float* Ap  = img + (size_t)(m0 + lrow) * D_ + lc * 4;
    const float* Ap2 = Ap + (size_t)64 * D_;
    const float* Wp  = Wx + (size_t)(n0 + lrow) * D_ + lc * 4;
    const float* Wp2 = Wp + (size_t)64 * D_;

    float acc[8][8] = {};
    float4 a0 = *(const float4*)Ap;
    float4 a1 = *(const float4*)Ap2;
    float4 w0 = *(const float4*)Wp;
    float4 w1 = *(const float4*)Wp2;

    int buf = 0;
    #define XST(BUF) do { \
        As[BUF][lc*4+0][lrow]=a0.x; As[BUF][lc*4+1][lrow]=a0.y; As[BUF][lc*4+2][lrow]=a0.z; As[BUF][lc*4+3][lrow]=a0.w; \
        As[BUF][lc*4+0][lrow+64]=a1.x; As[BUF][lc*4+1][lrow+64]=a1.y; As[BUF][lc*4+2][lrow+64]=a1.z; As[BUF][lc*4+3][lrow+64]=a1.w; \
        Bs[BUF][lc*4+0][lrow]=w0.x; Bs[BUF][lc*4+1][lrow]=w0.y; Bs[BUF][lc*4+2][lrow]=w0.z; Bs[BUF][lc*4+3][lrow]=w0.w; \
        Bs[BUF][lc*4+0][lrow+64]=w1.x; Bs[BUF][lc*4+1][lrow+64]=w1.y; Bs[BUF][lc*4+2][lrow+64]=w1.z; Bs[BUF][lc*4+3][lrow+64]=w1.w; \
    } while(0)
    #define XCOMP(BUF) do { \
        _Pragma("unroll") \
        for (int kk = 0; kk < 16; kk++) { \
            float4 av0 = *(const float4*)&As[BUF][kk][ty*8]; \
            float4 av1 = *(const float4*)&As[BUF][kk][ty*8+4]; \
            float4 bv0 = *(const float4*)&Bs[BUF][kk][tx*8]; \
            float4 bv1 = *(const float4*)&Bs[BUF][kk][tx*8+4]; \
            float ar[8] = {av0.x,av0.y,av0.z,av0.w,av1.x,av1.y,av1.z,av1.w}; \
            float br[8] = {bv0.x,bv0.y,bv0.z,bv0.w,bv1.x,bv1.y,bv1.z,bv1.w}; \
            _Pragma("unroll") \
            for (int i = 0; i < 8; i++) \
                _Pragma("unroll") \
                for (int j = 0; j < 8; j++) acc[i][j] += ar[i]*br[j]; \
        } \
    } while(0)

    XST(0);
    __syncthreads();
    for (int k0 = 16; k0 < D_; k0 += 16) {
        a0 = *(const float4*)(Ap + k0);
        a1 = *(const float4*)(Ap2 + k0);
        w0 = *(const float4*)(Wp + k0);
        w1 = *(const float4*)(Wp2 + k0);
        if (buf == 0) { XCOMP(0); XST(1); } else { XCOMP(1); XST(0); }
        __syncthreads();
        buf ^= 1;
    }
    if (buf == 0) XCOMP(0); else XCOMP(1);

    float bxr[8];
    #pragma unroll
    for (int j = 0; j < 8; j++) bxr[j] = bx[n0 + tx * 8 + j];
    #pragma unroll
    for (int i = 0; i < 8; i++) {
        int m = m0 + ty * 8 + i;
        int b = m >> 6, t = m & 63;
        #pragma unroll
        for (int j = 0; j < 8; j++) {
            int a = n0 + tx * 8 + j;
            g_xProjT[(size_t)b * (A_ * T_) + a * T_ + t] = acc[i][j] + bxr[j];
        }
    }
    #undef XST
    #undef XCOMP
}

// ---------------- per-step GEMM (gi/gh halves, split-K) ----------------
__global__ __launch_bounds__(256) void step_gemm(const float* __restrict__ Whh) {
    __shared__ float As[2][16][68];
    __shared__ float Bs[2][16][68];
    const int z = blockIdx.z;
    const float* A; int as_; const float* W; int ws_; float* C; int koff, klen;
    if (z < 2) { A = g_ctx; as_ = D_; W = g_WihCtx; ws_ = D_;
                 C = z ? g_gi1 : g_gi0; koff = z * 256; klen = 256; }
    else       { A = g_h;   as_ = H_; W = Whh;      ws_ = H_;
                 C = (z == 3) ? g_gh1 : g_gh0; koff = (z - 2) * 128; klen = 128; }

    const int tid = threadIdx.x;
    const int tx = tid & 15, ty = tid >> 4;
    const int lrow = tid >> 2, lc = tid & 3;
    const int n0 = blockIdx.x * 64;
    const int m0 = blockIdx.y * 64;

    float acc[4][4] = {};
    const float* Ap = A + (size_t)(m0 + lrow) * as_ + koff + lc * 4;
    const float* Wp = W + (size_t)(n0 + lrow) * ws_ + koff + lc * 4;
    float4 av = *(const float4*)Ap;
    float4 bv = *(const float4*)Wp;

    #define GST(BUF) do { \
        As[BUF][lc*4+0][lrow]=av.x; As[BUF][lc*4+1][lrow]=av.y; As[BUF][lc*4+2][lrow]=av.z; As[BUF][lc*4+3][lrow]=av.w; \
        Bs[BUF][lc*4+0][lrow]=bv.x; Bs[BUF][lc*4+1][lrow]=bv.y; Bs[BUF][lc*4+2][lrow]=bv.z; Bs[BUF][lc*4+3][lrow]=bv.w; \
    } while(0)
    #define GCOMP(BUF) do { \
        _Pragma("unroll") \
        for (int kk = 0; kk < 16; kk++) { \
            float4 a4 = *(const float4*)&As[BUF][kk][ty*4]; \
            float4 b4 = *(const float4*)&Bs[BUF][kk][tx*4]; \
            float ar[4] = {a4.x,a4.y,a4.z,a4.w}; \
            float br[4] = {b4.x,b4.y,b4.z,b4.w}; \
            _Pragma("unroll") \
            for (int i = 0; i < 4; i++) \
                _Pragma("unroll") \
                for (int j = 0; j < 4; j++) acc[i][j] += ar[i]*br[j]; \
        } \
    } while(0)

    GST(0);
    __syncthreads();
    int buf = 0;
    for (int k0 = 16; k0 < klen; k0 += 16) {
        av = *(const float4*)(Ap + k0);
        bv = *(const float4*)(Wp + k0);
        if (buf == 0) { GCOMP(0); GST(1); } else { GCOMP(1); GST(0); }
        __syncthreads();
        buf ^= 1;
    }
    if (buf == 0) GCOMP(0); else GCOMP(1);

    #pragma unroll
    for (int i = 0; i < 4; i++) {
        float4 o4 = {acc[i][0], acc[i][1], acc[i][2], acc[i][3]};
        *(float4*)(C + (size_t)(m0 + ty * 4 + i) * H3_ + n0 + tx * 4) = o4;
    }
    #undef GST
    #undef GCOMP
}

// ---------------- gates + FC + sProj (weight-reuse kernel, 4 rows/block) ----
__global__ __launch_bounds__(256) void gates_kernel(int step,
                           const int*   __restrict__ label,
                           const float* __restrict__ bs,
                           const float* __restrict__ bhh,
                           const float* __restrict__ bfc,
                           float* __restrict__ out) {
    __shared__ float hs[4][H_];
    const int tid = threadIdx.x;
    const int b0  = blockIdx.x * 4;

    // ---- GRU gates ----
    if (step > 0) {
        for (int i = tid; i < 4 * H_; i += 256) {
            int b = i >> 8, j = i & 255, row = b0 + b;
            int yp = (step == 1) ? 0 : label[row * STEPS_ + step - 1];
            const float* ep = g_embProj + (size_t)yp * H3_;
            size_t o = (size_t)row * H3_ + j;
            float gir = ep[j]          + g_gi0[o]          + g_gi1[o];
            float giz = ep[H_ + j]     + g_gi0[o + H_]     + g_gi1[o + H_];
            float gin = ep[2 * H_ + j] + g_gi0[o + 2 * H_] + g_gi1[o + 2 * H_];
            float ghr = g_gh0[o]          + g_gh1[o]          + bhh[j];
            float ghz = g_gh0[o + H_]     + g_gh1[o + H_]     + bhh[H_ + j];
            float ghn = g_gh0[o + 2 * H_] + g_gh1[o + 2 * H_] + bhh[2 * H_ + j];
            float r  = fma_sigmoid(gir + ghr);
            float zz = fma_sigmoid(giz + ghz);
            float nn = fma_tanh(gin + r * ghn);
            float hp = g_h[(size_t)row * H_ + j];
            float hn = (1.0f - zz) * nn + zz * hp;
            hs[b][j] = hn;
            g_h[(size_t)row * H_ + j] = hn;
        }
        __syncthreads();
        // ---- FC out for step-1 ----
        for (int idx = tid; idx < 4 * C_; idx += 256) {
            int b = idx / C_, c = idx - b * C_;
            float acc = bfc[c];
            #pragma unroll 8
            for (int k = 0; k < H_; k++) acc += g_WfcT[k * C_ + c] * hs[b][k];
            out[((size_t)(b0 + b) * STEPS_ + step - 1) * C_ + c] = acc;
        }
        if (step >= STEPS_) return;
        // ---- sProj ----
        {
            int a = tid;
            float a0 = 0.f, a1 = 0.f, a2 = 0.f, a3 = 0.f;
            #pragma unroll 4
            for (int k = 0; k < H_; k++) {
                float wv = g_WsT[k * A_ + a];
                a0 += wv * hs[0][k]; a1 += wv * hs[1][k];
                a2 += wv * hs[2][k]; a3 += wv * hs[3][k];
            }
            float bb = bs[a];
            g_sp[(size_t)(b0 + 0) * A_ + a] = a0 + bb;
            g_sp[(size_t)(b0 + 1) * A_ + a] = a1 + bb;
            g_sp[(size_t)(b0 + 2) * A_ + a] = a2 + bb;
            g_sp[(size_t)(b0 + 3) * A_ + a] = a3 + bb;
        }
    } else {
        // step 0: h = 0 -> sProj = bs
        for (int i = tid; i < 4 * A_; i += 256)
            g_sp[(size_t)b0 * A_ + i] = bs[i & 255];
    }
}

// ---------------- scores + softmax + ctx (1 row/block, 512 blocks) --------
__global__ __launch_bounds__(256) void ctx_kernel(const float* __restrict__ img,
                                                  const float* __restrict__ Ww,
                                                  const float* __restrict__ bw) {
    __shared__ float sp_s[A_];
    __shared__ float ww_s[A_];
    __shared__ float part[256];
    __shared__ float vb_s[T_];
    __shared__ float al_s[T_];
    const int b = blockIdx.x;
    const int tid = threadIdx.x;

    sp_s[tid] = g_sp[(size_t)b * A_ + tid];
    ww_s[tid] = Ww[tid];
    __syncthreads();

    // scores: thread = (a-chunk, t); 4 chunks of 64 a's
    {
        int t = tid & 63, ac = tid >> 6;
        const float* xp = g_xProjT + (size_t)b * (A_ * T_) + (ac * 64) * T_ + t;
        const float* spp = sp_s + ac * 64;
        const float* wwp = ww_s + ac * 64;
        float acc = 0.0f;
        #pragma unroll 8
        for (int i = 0; i < 64; i++)
            acc += fma_tanh(spp[i] + xp[(size_t)i * T_]) * wwp[i];
        part[tid] = acc;
    }
    __syncthreads();
    if (tid < T_)
        vb_s[tid] = part[tid] + part[tid + 64] + part[tid + 128] + part[tid + 192] + bw[0];
    __syncthreads();
    if (tid < 32) {
        float v0 = vb_s[tid], v1 = vb_s[tid + 32];
        float m = warp_max(fmaxf(v0, v1));
        float e0 = __expf(v0 - m), e1 = __expf(v1 - m);
        float s = warp_sum(e0 + e1);
        float inv = 1.0f / s;
        al_s[tid]      = e0 * inv;
        al_s[tid + 32] = e1 * inv;
    }
    __syncthreads();

    // ctx: thread owns one float2 of D
    {
        const float2* ib = (const float2*)img + (size_t)b * T_ * (D_ / 2) + tid;
        float2 acc = {0.f, 0.f};
        #pragma unroll 8
        for (int t = 0; t < T_; t++) {
            float a = al_s[t];
            float2 iv = ib[(size_t)t * (D_ / 2)];
            acc.x += a * iv.x; acc.y += a * iv.y;
        }
        *(float2*)(g_ctx + (size_t)b * D_ + tid * 2) = acc;
    }
}

// ---------------- host launch ----------------
extern "C" void kernel_launch(void* const* d_in, const int* in_sizes, int n_in,
                              void* d_out, int out_size) {
    const float* img   = (const float*)d_in[0];
    const int*   label = (const int*)  d_in[1];
    const float* Wx    = (const float*)d_in[2];
    const float* bx    = (const float*)d_in[3];
    const float* Ws    = (const float*)d_in[4];
    const float* bs    = (const float*)d_in[5];
    const float* Ww    = (const float*)d_in[6];
    const float* bw    = (const float*)d_in[7];
    const float* emb   = (const float*)d_in[8];
    const float* Wih   = (const float*)d_in[9];
    const float* bih   = (const float*)d_in[10];
    const float* Whh   = (const float*)d_in[11];
    const float* bhh   = (const float*)d_in[12];
    const float* Wfc   = (const float*)d_in[13];
    const float* bfc   = (const float*)d_in[14];
    float* out = (float*)d_out;

    setup_kernel<<<512, 256>>>(Ws, Wfc, Wih);
    embproj_kernel<<<C_ + 1, 256>>>(emb, bih);

    dim3 gx(A_ / 128, (B_ * T_) / 128);
    xproj_kernel<<<gx, 256>>>(img, Wx, bx);

    dim3 gg(H3_ / 64, B_ / 64, 4);
    for (int s = 0; s < STEPS_; s++) {
        gates_kernel<<<B_ / 4, 256>>>(s, label, bs, bhh, bfc, out);
        ctx_kernel<<<B_, 256>>>(img, Ww, bw);
        step_gemm<<<gg, 256>>>(Whh);
    }
    gates_kernel<<<B_ / 4, 256>>>(STEPS_, label, bs, bhh, bfc, out);
}

// round 5
// speedup vs baseline: 1.8981x; 1.0316x over previous
#include <cuda_runtime.h>
#include <cuda_bf16.h>
#include <cstdint>

#define B_ 512
#define T_ 64
#define D_ 512
#define H_ 256
#define A_ 256
#define C_ 96
#define STEPS_ 26
#define H3_ 768

// ---------------- device scratch ----------------
__device__ float g_xProjT[(size_t)B_ * A_ * T_];   // [B, A, T] fp32
__device__ float g_h[B_ * H_];
__device__ float g_sp[B_ * A_];
__device__ float g_gi[B_ * H3_];
__device__ float g_gh[B_ * H3_];
__device__ float g_WsT[H_ * A_];
__device__ float g_WfcT[H_ * C_];
__device__ float g_WihEmbT[A_ * H3_];
__device__ float g_embProj[(C_ + 1) * H3_];
// split-bf16 operand storage
__device__ __nv_bfloat16 g_WxHi[A_ * D_],  g_WxLo[A_ * D_];
__device__ __nv_bfloat16 g_WicHi[H3_ * D_], g_WicLo[H3_ * D_];
__device__ __nv_bfloat16 g_WhhHi[H3_ * H_], g_WhhLo[H3_ * H_];
__device__ __nv_bfloat16 g_ctxHi[B_ * D_],  g_ctxLo[B_ * D_];
__device__ __nv_bfloat16 g_hHi[B_ * H_],   g_hLo[B_ * H_];

// ---------------- math helpers ----------------
__device__ __forceinline__ float fma_tanh(float x) {
    x = fminf(3.2f, fmaxf(-3.2f, x));
    float u = x * x;
    float num = x * (945.0f + u * (105.0f + u));
    float den = 945.0f + u * (420.0f + u * 15.0f);
    float y = 1.0582e-3f + u * (-2.1408e-4f + u * 1.2184e-5f);
    y = y * (2.0f - den * y);
    y = y * (2.0f - den * y);
    y = y * (2.0f - den * y);
    return num * y;
}
__device__ __forceinline__ float fma_sigmoid(float x) {
    return 0.5f + 0.5f * fma_tanh(0.5f * x);
}
__device__ __forceinline__ float warp_sum(float v) {
    #pragma unroll
    for (int o = 16; o; o >>= 1) v += __shfl_xor_sync(0xffffffffu, v, o);
    return v;
}
__device__ __forceinline__ float warp_max(float v) {
    #pragma unroll
    for (int o = 16; o; o >>= 1) v = fmaxf(v, __shfl_xor_sync(0xffffffffu, v, o));
    return v;
}

// ---------------- mma.sync helpers (baseline PTX, sm_80+) ----------------
__device__ __forceinline__ uint32_t smem_addr_u32(const void* p) {
    uint32_t a;
    asm("{ .reg .u64 t; cvta.to.shared.u64 t, %1; cvt.u32.u64 %0, t; }" : "=r"(a) : "l"(p));
    return a;
}
__device__ __forceinline__ void ldsm4(uint32_t a[4], uint32_t addr) {
    asm volatile("ldmatrix.sync.aligned.m8n8.x4.shared.b16 {%0,%1,%2,%3}, [%4];"
        : "=r"(a[0]), "=r"(a[1]), "=r"(a[2]), "=r"(a[3]) : "r"(addr));
}
__device__ __forceinline__ void ldsm2(uint32_t b[2], uint32_t addr) {
    asm volatile("ldmatrix.sync.aligned.m8n8.x2.shared.b16 {%0,%1}, [%2];"
        : "=r"(b[0]), "=r"(b[1]) : "r"(addr));
}
__device__ __forceinline__ void mma16816(float c[4], const uint32_t a[4], const uint32_t b[2]) {
    asm volatile("mma.sync.aligned.m16n8k16.row.col.f32.bf16.bf16.f32 "
        "{%0,%1,%2,%3}, {%4,%5,%6,%7}, {%8,%9}, {%0,%1,%2,%3};"
        : "+f"(c[0]), "+f"(c[1]), "+f"(c[2]), "+f"(c[3])
        : "r"(a[0]), "r"(a[1]), "r"(a[2]), "r"(a[3]), "r"(b[0]), "r"(b[1]));
}
#define SWZ(o) ((o) ^ (((o) >> 3) & 0x70))

__device__ __forceinline__ void split_f8(const float* v, uint4& hi, uint4& lo) {
    __nv_bfloat162* hp = (__nv_bfloat162*)&hi;
    __nv_bfloat162* lp = (__nv_bfloat162*)&lo;
    #pragma unroll
    for (int j = 0; j < 4; j++) {
        float x = v[2 * j], y = v[2 * j + 1];
        __nv_bfloat16 hx = __float2bfloat16(x), hy = __float2bfloat16(y);
        hp[j].x = hx; hp[j].y = hy;
        lp[j].x = __float2bfloat16(x - __bfloat162float(hx));
        lp[j].y = __float2bfloat16(y - __bfloat162float(hy));
    }
}

// ---------------- setup: transposes + bf16 splits + zero state ----------------
__global__ void setup_kernel(const float* __restrict__ Ws,
                             const float* __restrict__ Wfc,
                             const float* __restrict__ Wih,
                             const float* __restrict__ Wx,
                             const float* __restrict__ Whh) {
    int idx = blockIdx.x * 256 + threadIdx.x;
    int stride = gridDim.x * 256;
    for (int i = idx; i < B_ * H_; i += stride) {
        g_h[i] = 0.0f;
        g_hHi[i] = __float2bfloat16(0.0f);
        g_hLo[i] = __float2bfloat16(0.0f);
    }
    for (int i = idx; i < H_ * A_; i += stride) {
        int k = i >> 8, a = i & 255;
        g_WsT[i] = Ws[a * H_ + k];
    }
    for (int i = idx; i < H_ * C_; i += stride) {
        int k = i / C_, c = i - k * C_;
        g_WfcT[i] = Wfc[c * H_ + k];
    }
    for (int i = idx; i < A_ * H3_; i += stride) {
        int k = i / H3_, n = i - k * H3_;
        g_WihEmbT[i] = Wih[n * (D_ + A_) + k];
    }
    for (int i = idx; i < A_ * D_; i += stride) {
        float x = Wx[i];
        __nv_bfloat16 h = __float2bfloat16(x);
        g_WxHi[i] = h;
        g_WxLo[i] = __float2bfloat16(x - __bfloat162float(h));
    }
    for (int i = idx; i < H3_ * D_; i += stride) {
        int n = i >> 9, k = i & 511;
        float x = Wih[n * (D_ + A_) + A_ + k];
        __nv_bfloat16 h = __float2bfloat16(x);
        g_WicHi[i] = h;
        g_WicLo[i] = __float2bfloat16(x - __bfloat162float(h));
    }
    for (int i = idx; i < H3_ * H_; i += stride) {
        float x = Whh[i];
        __nv_bfloat16 h = __float2bfloat16(x);
        g_WhhHi[i] = h;
        g_WhhLo[i] = __float2bfloat16(x - __bfloat162float(h));
    }
}

__global__ __launch_bounds__(256) void embproj_kernel(const float* __restrict__ emb,
                                                      const float* __restrict__ bih) {
    __shared__ float es[A_];
    int y = blockIdx.x, tid = threadIdx.x;
    es[tid] = emb[y * A_ + tid];
    __syncthreads();
    for (int nn = tid; nn < H3_; nn += 256) {
        float acc = bih[nn];
        #pragma unroll 8
        for (int k = 0; k < A_; k++) acc += g_WihEmbT[k * H3_ + nn] * es[k];
        g_embProj[y * H3_ + nn] = acc;
    }
}

// smem offsets for MMA kernels: 4 tiles of 128x64 bf16 (16 KB each)
#define MM_AHI 0
#define MM_ALO 16384
#define MM_BHI 32768
#define MM_BLO 49152
#define MM_DYN (65536 + 1024)

// ---------------- xproj via mma.sync: per CTA M=128, N=128, K=512 ----------------
__global__ __launch_bounds__(256, 1) void xproj_mma_kernel(const float* __restrict__ img,
                                                           const float* __restrict__ bx) {
    extern __shared__ char dynsm[];
    __shared__ float s_bx[128];
    const int tid = threadIdx.x;
    const int lane = tid & 31;
    const int w = tid >> 5;
    const int n0 = blockIdx.x * 128;
    const int m0 = blockIdx.y * 128;

    uint32_t dynb = smem_addr_u32(dynsm);
    uint32_t smb = (dynb + 1023) & ~1023u;
    char* sm = dynsm + (smb - dynb);

    if (tid < 128) s_bx[tid] = bx[n0 + tid];

    const int wm = (w & 1) * 64;
    const int wn = (w >> 1) * 32;
    float acc[4][4][4] = {};

    for (int c = 0; c < 8; c++) {
        const int k0 = c * 64;
        __syncthreads();
        // A: img fp32 -> split bf16, 128 rows x 64 cols
        #pragma unroll
        for (int it = 0; it < 4; it++) {
            int idx = it * 256 + tid;
            int r = idx >> 3, j8 = idx & 7;
            const float* src = img + (size_t)(m0 + r) * D_ + k0 + j8 * 8;
            float v[8];
            *(float4*)&v[0] = *(const float4*)src;
            *(float4*)&v[4] = *(const float4*)(src + 4);
            uint4 hi, lo;
            split_f8(v, hi, lo);
            uint32_t off = SWZ((uint32_t)(r * 128 + j8 * 16));
            *(uint4*)(sm + MM_AHI + off) = hi;
            *(uint4*)(sm + MM_ALO + off) = lo;
        }
        // B: pre-split Wx, 128 rows x 64 cols
        #pragma unroll
        for (int it = 0; it < 4; it++) {
            int idx = it * 256 + tid;
            int r = idx >> 3, j8 = idx & 7;
            uint32_t off = SWZ((uint32_t)(r * 128 + j8 * 16));
            *(uint4*)(sm + MM_BHI + off) = *(const uint4*)(g_WxHi + (size_t)(n0 + r) * D_ + k0 + j8 * 8);
            *(uint4*)(sm + MM_BLO + off) = *(const uint4*)(g_WxLo + (size_t)(n0 + r) * D_ + k0 + j8 * 8);
        }
        __syncthreads();

        #pragma unroll
        for (int ks = 0; ks < 4; ks++) {
            uint32_t bh[4][2], bl[4][2];
            #pragma unroll
            for (int nj = 0; nj < 4; nj++) {
                int rr = wn + nj * 8 + (lane & 7);
                uint32_t cb = ks * 32 + ((lane >> 3) & 1) * 16;
                uint32_t ad = SWZ((uint32_t)(rr * 128) + cb);
                ldsm2(bh[nj], smb + MM_BHI + ad);
                ldsm2(bl[nj], smb + MM_BLO + ad);
            }
            #pragma unroll
            for (int mi = 0; mi < 4; mi++) {
                int rr = wm + mi * 16 + (lane & 15);
                uint32_t cb = ks * 32 + (lane >> 4) * 16;
                uint32_t ad = SWZ((uint32_t)(rr * 128) + cb);
                uint32_t ah[4], al[4];
                ldsm4(ah, smb + MM_AHI + ad);
                ldsm4(al, smb + MM_ALO + ad);
                #pragma unroll
                for (int nj = 0; nj < 4; nj++) {
                    mma16816(acc[mi][nj], ah, bh[nj]);
                    mma16816(acc[mi][nj], al, bh[nj]);
                    mma16816(acc[mi][nj], ah, bl[nj]);
                }
            }
        }
    }

    // epilogue: c0:(r,c) c1:(r,c+1) c2:(r+8,c) c3:(r+8,c+1); store to xProjT[b][a][t]
    #pragma unroll
    for (int mi = 0; mi < 4; mi++) {
        int mr = m0 + wm + mi * 16 + (lane >> 2);
        int b0i = mr >> 6, t0 = mr & 63;
        int b1i = (mr + 8) >> 6, t1 = (mr + 8) & 63;
        #pragma unroll
        for (int nj = 0; nj < 4; nj++) {
            int ncl = wn + nj * 8 + (lane & 3) * 2;
            int nc = n0 + ncl;
            float bx0 = s_bx[ncl], bx1 = s_bx[ncl + 1];
            g_xProjT[(size_t)b0i * (A_ * T_) + (size_t)nc * T_ + t0]       = acc[mi][nj][0] + bx0;
            g_xProjT[(size_t)b0i * (A_ * T_) + (size_t)(nc + 1) * T_ + t0] = acc[mi][nj][1] + bx1;
            g_xProjT[(size_t)b1i * (A_ * T_) + (size_t)nc * T_ + t1]       = acc[mi][nj][2] + bx0;
            g_xProjT[(size_t)b1i * (A_ * T_) + (size_t)(nc + 1) * T_ + t1] = acc[mi][nj][3] + bx1;
        }
    }
}

// ---------------- per-step gi/gh via mma.sync: 48 CTAs, M=128, N=128 ----------------
__global__ __launch_bounds__(256, 1) void step_mma_kernel() {
    extern __shared__ char dynsm[];
    const int tid = threadIdx.x;
    const int lane = tid & 31;
    const int w = tid >> 5;

    int zz = blockIdx.x;
    const __nv_bfloat16 *Ahi, *Alo, *Bhi, *Blo;
    int lda, ldb, nch, m0, n0;
    float* Cout;
    if (zz < 24) {
        int mt = zz / 6, nt = zz % 6;
        m0 = mt * 128; n0 = nt * 128;
        Ahi = g_ctxHi; Alo = g_ctxLo; lda = D_;
        Bhi = g_WicHi; Blo = g_WicLo; ldb = D_;
        nch = 8; Cout = g_gi;
    } else {
        zz -= 24;
        int mt = zz / 6, nt = zz % 6;
        m0 = mt * 128; n0 = nt * 128;
        Ahi = g_hHi; Alo = g_hLo; lda = H_;
        Bhi = g_WhhHi; Blo = g_WhhLo; ldb = H_;
        nch = 4; Cout = g_gh;
    }

    uint32_t dynb = smem_addr_u32(dynsm);
    uint32_t smb = (dynb + 1023) & ~1023u;
    char* sm = dynsm + (smb - dynb);

    const int wm = (w & 1) * 64;
    const int wn = (w >> 1) * 32;
    float acc[4][4][4] = {};

    for (int c = 0; c < nch; c++) {
        const int k0 = c * 64;
        __syncthreads();
        #pragma unroll
        for (int it = 0; it < 4; it++) {
            int idx = it * 256 + tid;
            int r = idx >> 3, j8 = idx & 7;
            uint32_t off = SWZ((uint32_t)(r * 128 + j8 * 16));
            *(uint4*)(sm + MM_AHI + off) = *(const uint4*)(Ahi + (size_t)(m0 + r) * lda + k0 + j8 * 8);
            *(uint4*)(sm + MM_ALO + off) = *(const uint4*)(Alo + (size_t)(m0 + r) * lda + k0 + j8 * 8);
            *(uint4*)(sm + MM_BHI + off) = *(const uint4*)(Bhi + (size_t)(n0 + r) * ldb + k0 + j8 * 8);
            *(uint4*)(sm + MM_BLO + off) = *(const uint4*)(Blo + (size_t)(n0 + r) * ldb + k0 + j8 * 8);
        }
        __syncthreads();

        #pragma unroll
        for (int ks = 0; ks < 4; ks++) {
            uint32_t bh[4][2], bl[4][2];
            #pragma unroll
            for (int nj = 0; nj < 4; nj++) {
                int rr = wn + nj * 8 + (lane & 7);
                uint32_t cb = ks * 32 + ((lane >> 3) & 1) * 16;
                uint32_t ad = SWZ((uint32_t)(rr * 128) + cb);
                ldsm2(bh[nj], smb + MM_BHI + ad);
                ldsm2(bl[nj], smb + MM_BLO + ad);
            }
            #pragma unroll
            for (int mi = 0; mi < 4; mi++) {
                int rr = wm + mi * 16 + (lane & 15);
                uint32_t cb = ks * 32 + (lane >> 4) * 16;
                uint32_t ad = SWZ((uint32_t)(rr * 128) + cb);
                uint32_t ah[4], al[4];
                ldsm4(ah, smb + MM_AHI + ad);
                ldsm4(al, smb + MM_ALO + ad);
                #pragma unroll
                for (int nj = 0; nj < 4; nj++) {
                    mma16816(acc[mi][nj], ah, bh[nj]);
                    mma16816(acc[mi][nj], al, bh[nj]);
                    mma16816(acc[mi][nj], ah, bl[nj]);
                }
            }
        }
    }

    #pragma unroll
    for (int mi = 0; mi < 4; mi++) {
        int mr = m0 + wm + mi * 16 + (lane >> 2);
        #pragma unroll
        for (int nj = 0; nj < 4; nj++) {
            int nc = n0 + wn + nj * 8 + (lane & 3) * 2;
            float2 o0 = {acc[mi][nj][0], acc[mi][nj][1]};
            float2 o1 = {acc[mi][nj][2], acc[mi][nj][3]};
            *(float2*)(Cout + (size_t)mr * H3_ + nc) = o0;
            *(float2*)(Cout + (size_t)(mr + 8) * H3_ + nc) = o1;
        }
    }
}

// ---------------- gates + FC + sProj ----------------
__global__ __launch_bounds__(256) void gates_kernel(int step,
                           const int*   __restrict__ label,
                           const float* __restrict__ bs,
                           const float* __restrict__ bhh,
                           const float* __restrict__ bfc,
                           float* __restrict__ out) {
    __shared__ float hs[4][H_];
    const int tid = threadIdx.x;
    const int b0  = blockIdx.x * 4;

    if (step > 0) {
        for (int i = tid; i < 4 * H_; i += 256) {
            int b = i >> 8, j = i & 255, row = b0 + b;
            int yp = (step == 1) ? 0 : label[row * STEPS_ + step - 1];
            const float* ep = g_embProj + (size_t)yp * H3_;
            const float* gi = g_gi + (size_t)row * H3_;
            const float* gh = g_gh + (size_t)row * H3_;
            float gir = ep[j]          + gi[j];
            float giz = ep[H_ + j]     + gi[H_ + j];
            float gin = ep[2 * H_ + j] + gi[2 * H_ + j];
            float ghr = gh[j]          + bhh[j];
            float ghz = gh[H_ + j]     + bhh[H_ + j];
            float ghn = gh[2 * H_ + j] + bhh[2 * H_ + j];
            float r  = fma_sigmoid(gir + ghr);
            float zz = fma_sigmoid(giz + ghz);
            float nn = fma_tanh(gin + r * ghn);
            float hp = g_h[(size_t)row * H_ + j];
            float hn = (1.0f - zz) * nn + zz * hp;
            hs[b][j] = hn;
            g_h[(size_t)row * H_ + j] = hn;
            __nv_bfloat16 hh = __float2bfloat16(hn);
            g_hHi[(size_t)row * H_ + j] = hh;
            g_hLo[(size_t)row * H_ + j] = __float2bfloat16(hn - __bfloat162float(hh));
        }
        __syncthreads();
        for (int idx = tid; idx < 4 * C_; idx += 256) {
            int b = idx / C_, c = idx - b * C_;
            float acc = bfc[c];
            #pragma unroll 8
            for (int k = 0; k < H_; k++) acc += g_WfcT[k * C_ + c] * hs[b][k];
            out[((size_t)(b0 + b) * STEPS_ + step - 1) * C_ + c] = acc;
        }
        if (step >= STEPS_) return;
        {
            int a = tid;
            float a0 = 0.f, a1 = 0.f, a2 = 0.f, a3 = 0.f;
            #pragma unroll 4
            for (int k = 0; k < H_; k++) {
                float wv = g_WsT[k * A_ + a];
                a0 += wv * hs[0][k]; a1 += wv * hs[1][k];
                a2 += wv * hs[2][k]; a3 += wv * hs[3][k];
            }
            float bb = bs[a];
            g_sp[(size_t)(b0 + 0) * A_ + a] = a0 + bb;
            g_sp[(size_t)(b0 + 1) * A_ + a] = a1 + bb;
            g_sp[(size_t)(b0 + 2) * A_ + a] = a2 + bb;
            g_sp[(size_t)(b0 + 3) * A_ + a] = a3 + bb;
        }
    } else {
        for (int i = tid; i < 4 * A_; i += 256)
            g_sp[(size_t)b0 * A_ + i] = bs[i & 255];
    }
}

// ---------------- scores + softmax + ctx (writes split ctx) ----------------
__global__ __launch_bounds__(256) void ctx_kernel(const float* __restrict__ img,
                                                  const float* __restrict__ Ww,
                                                  const float* __restrict__ bw) {
    __shared__ float sp_s[A_];
    __shared__ float ww_s[A_];
    __shared__ float part[256];
    __shared__ float vb_s[T_];
    __shared__ float al_s[T_];
    const int b = blockIdx.x;
    const int tid = threadIdx.x;

    sp_s[tid] = g_sp[(size_t)b * A_ + tid];
    ww_s[tid] = Ww[tid];
    __syncthreads();

    {
        int t = tid & 63, ac = tid >> 6;
        const float* xp = g_xProjT + (size_t)b * (A_ * T_) + (ac * 64) * T_ + t;
        const float* spp = sp_s + ac * 64;
        const float* wwp = ww_s + ac * 64;
        float acc = 0.0f;
        #pragma unroll 8
        for (int i = 0; i < 64; i++)
            acc += fma_tanh(spp[i] + xp[(size_t)i * T_]) * wwp[i];
        part[tid] = acc;
    }
    __syncthreads();
    if (tid < T_)
        vb_s[tid] = part[tid] + part[tid + 64] + part[tid + 128] + part[tid + 192] + bw[0];
    __syncthreads();
    if (tid < 32) {
        float v0 = vb_s[tid], v1 = vb_s[tid + 32];
        float m = warp_max(fmaxf(v0, v1));
        float e0 = __expf(v0 - m), e1 = __expf(v1 - m);
        float s = warp_sum(e0 + e1);
        float inv = 1.0f / s;
        al_s[tid]      = e0 * inv;
        al_s[tid + 32] = e1 * inv;
    }
    __syncthreads();

    {
        const float2* ib = (const float2*)img + (size_t)b * T_ * (D_ / 2) + tid;
        float2 acc = {0.f, 0.f};
        #pragma unroll 8
        for (int t = 0; t < T_; t++) {
            float a = al_s[t];
            float2 iv = ib[(size_t)t * (D_ / 2)];
            acc.x += a * iv.x; acc.y += a * iv.y;
        }
        __nv_bfloat16 h0 = __float2bfloat16(acc.x);
        __nv_bfloat16 h1 = __float2bfloat16(acc.y);
        __nv_bfloat162 hp; hp.x = h0; hp.y = h1;
        __nv_bfloat162 lp;
        lp.x = __float2bfloat16(acc.x - __bfloat162float(h0));
        lp.y = __float2bfloat16(acc.y - __bfloat162float(h1));
        *(__nv_bfloat162*)(g_ctxHi + (size_t)b * D_ + tid * 2) = hp;
        *(__nv_bfloat162*)(g_ctxLo + (size_t)b * D_ + tid * 2) = lp;
    }
}

// ---------------- host launch ----------------
extern "C" void kernel_launch(void* const* d_in, const int* in_sizes, int n_in,
                              void* d_out, int out_size) {
    const float* img   = (const float*)d_in[0];
    const int*   label = (const int*)  d_in[1];
    const float* Wx    = (const float*)d_in[2];
    const float* bx    = (const float*)d_in[3];
    const float* Ws    = (const float*)d_in[4];
    const float* bs    = (const float*)d_in[5];
    const float* Ww    = (const float*)d_in[6];
    const float* bw    = (const float*)d_in[7];
    const float* emb   = (const float*)d_in[8];
    const float* Wih   = (const float*)d_in[9];
    const float* bih   = (const float*)d_in[10];
    const float* Whh   = (const float*)d_in[11];
    const float* bhh   = (const float*)d_in[12];
    const float* Wfc   = (const float*)d_in[13];
    const float* bfc   = (const float*)d_in[14];
    float* out = (float*)d_out;

    static bool attr_done = false;
    if (!attr_done) {
        cudaFuncSetAttribute(xproj_mma_kernel, cudaFuncAttributeMaxDynamicSharedMemorySize, MM_DYN);
        cudaFuncSetAttribute(step_mma_kernel,  cudaFuncAttributeMaxDynamicSharedMemorySize, MM_DYN);
        attr_done = true;
    }

    setup_kernel<<<512, 256>>>(Ws, Wfc, Wih, Wx, Whh);
    embproj_kernel<<<C_ + 1, 256>>>(emb, bih);

    dim3 gx(2, 256);   // n tiles x m tiles
    xproj_mma_kernel<<<gx, 256, MM_DYN>>>(img, bx);

    for (int s = 0; s < STEPS_; s++) {
        gates_kernel<<<B_ / 4, 256>>>(s, label, bs, bhh, bfc, out);
        ctx_kernel<<<B_, 256>>>(img, Ww, bw);
        step_mma_kernel<<<48, 256, MM_DYN>>>();
    }
    gates_kernel<<<B_ / 4, 256>>>(STEPS_, label, bs, bhh, bfc, out);
}